// round 7
// baseline (speedup 1.0000x reference)
#include <cuda_runtime.h>

#define IMG_W 512
#define IMG_H 512
#define N_IMG 48           // 16 batch * 3 channels
#define HT 8               // output rows per block strip
#define N_STRIPS (IMG_H / HT)
#define SW 528             // smem columns: x in [-8, 520), data valid x in [0,512)
#define NT 288             // 9 warps
#define SM_FLOATS (4 * HT * SW)
#define SMEM_BYTES ((SM_FLOATS + 16) * 4)

__device__ double g_acc;

__global__ void ssim_init() { g_acc = 0.0; }

__global__ void __launch_bounds__(NT, 2) ssim_main(const float* __restrict__ pred,
                                                   const float* __restrict__ tgt) {
    extern __shared__ float sm[];
    float* wsum = sm + SM_FLOATS;

    // 1-D Gaussian taps, sigma=1.5, k=11, normalized (compile-time immediates)
    const float wg[11] = {0.00102838f, 0.00759876f, 0.03600077f, 0.10936069f,
                          0.21300554f, 0.26601173f, 0.21300554f, 0.10936069f,
                          0.03600077f, 0.00759876f, 0.00102838f};

    const int img  = blockIdx.y;
    const int row0 = blockIdx.x * HT;
    const float* P = pred + (size_t)img * (IMG_W * IMG_H);
    const float* T = tgt  + (size_t)img * (IMG_W * IMG_H);

    // ---------------- Vertical pass: global -> smem (4 channels) ----------------
    for (int s = threadIdx.x; s < SW; s += NT) {
        const int x = s - 8;  // global column this smem slot represents
        if (x < 0 || x >= IMG_W) {
            // zero-padding columns (both the conv halo and the float4 alignment pad)
            #pragma unroll
            for (int r = 0; r < HT; r++) {
                sm[(0 * HT + r) * SW + s] = 0.f;
                sm[(1 * HT + r) * SW + s] = 0.f;
                sm[(2 * HT + r) * SW + s] = 0.f;
                sm[(3 * HT + r) * SW + s] = 0.f;
            }
        } else {
            float pv[HT + 10], tv[HT + 10], sv[HT + 10];
            #pragma unroll
            for (int i = 0; i < HT + 10; i++) {
                const int row = row0 - 5 + i;
                const bool ok = (row >= 0) && (row < IMG_H);
                float p = ok ? P[row * IMG_W + x] : 0.f;
                float t = ok ? T[row * IMG_W + x] : 0.f;
                pv[i] = p;
                tv[i] = t;
                sv[i] = fmaf(t, t, p * p);  // p^2 + t^2 combined channel
            }
            #pragma unroll
            for (int r = 0; r < HT; r++) {
                float mp = 0.f, mt = 0.f, ms = 0.f, mq = 0.f;
                #pragma unroll
                for (int k = 0; k < 11; k++) {
                    mp = fmaf(wg[k], pv[r + k], mp);
                    mt = fmaf(wg[k], tv[r + k], mt);
                    ms = fmaf(wg[k], sv[r + k], ms);
                    mq = fmaf(wg[k], pv[r + k] * tv[r + k], mq);
                }
                sm[(0 * HT + r) * SW + s] = mp;
                sm[(1 * HT + r) * SW + s] = mt;
                sm[(2 * HT + r) * SW + s] = ms;
                sm[(3 * HT + r) * SW + s] = mq;
            }
        }
    }
    __syncthreads();

    // ---------------- Horizontal pass + SSIM formula + reduce ----------------
    const float C1 = 1e-4f, C2 = 9e-4f;
    float acc = 0.f;
    // 128 quads (of 4 pixels) per row, HT rows
    for (int task = threadIdx.x; task < HT * (IMG_W / 4); task += NT) {
        const int r = task >> 7;       // row within strip
        const int q = task & 127;      // quad index: outputs x0 = 4q .. 4q+3
        float h[4][4];                 // [channel][pixel in quad]
        #pragma unroll
        for (int ch = 0; ch < 4; ch++) {
            const float4* rowp = (const float4*)(sm + (ch * HT + r) * SW);
            float v[20];
            #pragma unroll
            for (int b = 0; b < 5; b++) {
                float4 f = rowp[q + b];  // s = 4q + 4b .. covers taps x0-8 .. x0+11
                v[4 * b + 0] = f.x; v[4 * b + 1] = f.y;
                v[4 * b + 2] = f.z; v[4 * b + 3] = f.w;
            }
            #pragma unroll
            for (int j = 0; j < 4; j++) {
                float a = 0.f;
                #pragma unroll
                for (int k = 0; k < 11; k++) a = fmaf(wg[k], v[3 + j + k], a);
                h[ch][j] = a;
            }
        }
        #pragma unroll
        for (int j = 0; j < 4; j++) {
            float mx  = h[0][j], my = h[1][j];
            float mx2 = mx * mx, my2 = my * my, mxy = mx * my;
            float sgs  = h[2][j] - mx2 - my2;   // sg_x + sg_y
            float sgxy = h[3][j] - mxy;
            float num = (2.f * mxy + C1) * (2.f * sgxy + C2);
            float den = (mx2 + my2 + C1) * (sgs + C2);
            acc += __fdividef(num, den);
        }
    }

    // block reduction -> one double atomic per block
    #pragma unroll
    for (int off = 16; off; off >>= 1)
        acc += __shfl_down_sync(0xffffffffu, acc, off);
    if ((threadIdx.x & 31) == 0) wsum[threadIdx.x >> 5] = acc;
    __syncthreads();
    if (threadIdx.x == 0) {
        float s = 0.f;
        #pragma unroll
        for (int i = 0; i < NT / 32; i++) s += wsum[i];
        atomicAdd(&g_acc, (double)s);
    }
}

__global__ void ssim_final(float* out) {
    out[0] = 1.0f - (float)(g_acc / (double)(16.0 * 3.0 * 512.0 * 512.0));
}

extern "C" void kernel_launch(void* const* d_in, const int* in_sizes, int n_in,
                              void* d_out, int out_size) {
    const float* pred = (const float*)d_in[0];
    const float* tgt  = (const float*)d_in[1];

    // 66 KB dynamic smem > 48 KB default: opt-in (host attribute call, not a
    // stream op -> graph-capture safe, idempotent)
    cudaFuncSetAttribute(ssim_main, cudaFuncAttributeMaxDynamicSharedMemorySize,
                         SMEM_BYTES);

    ssim_init<<<1, 1>>>();
    dim3 grid(N_STRIPS, N_IMG);
    ssim_main<<<grid, NT, SMEM_BYTES>>>(pred, tgt);
    ssim_final<<<1, 1>>>((float*)d_out);
}